// round 10
// baseline (speedup 1.0000x reference)
#include <cuda_runtime.h>
#include <cuda_bf16.h>
#include <math.h>
#include <stdint.h>

// ---------------- problem constants ----------------
#define LSEQ   1024
#define BATCH  8
#define CDIM   256
#define DINNER 512
#define DSTATE 16
#define NROWS  (BATCH*LSEQ)   // 8192

typedef __nv_bfloat16 bf16;
typedef __nv_bfloat162 bf162;

// ---------------- scratch (static, no allocs) ----------------
__device__ __align__(256) bf16     g_xnh  [(size_t)NROWS*CDIM];
__device__ __align__(256) bf16     g_uh   [(size_t)NROWS*DINNER];
__device__ __align__(256) bf16     g_gzh  [(size_t)NROWS*DINNER];   // silu(z), [row][d]
__device__ __align__(256) bf16     g_u2h  [(size_t)NROWS*DINNER];
__device__ __align__(256) uint32_t g_du   [(size_t)NROWS*DINNER];   // (dt,u2) pack, [row][d]
__device__ __align__(256) float2   g_bc   [(size_t)NROWS*DSTATE];   // [row][s]
__device__ __align__(256) bf16     g_ygh  [(size_t)NROWS*DINNER];   // [row][d]
// weights, bf16, K-major [N][K]
__device__ __align__(256) bf16     g_WinT  [(size_t)1024*CDIM];
__device__ __align__(256) bf16     g_w2T   [(size_t)640*DINNER];    // [0:512)=wcomb, [512:544)=Wbc, rest 0
__device__ __align__(256) bf16     g_WoutT [(size_t)CDIM*DINNER];

// ---------------- small helpers ----------------
__device__ __forceinline__ float siluf(float v) { return v / (1.f + __expf(-v)); }
__device__ __forceinline__ float softplusf(float v) {
    return (v > 20.f) ? v : log1pf(__expf(v));
}
__device__ __forceinline__ uint32_t pbf2(float lo, float hi) {
    uint32_t r;
    asm("cvt.rn.bf16x2.f32 %0, %1, %2;" : "=r"(r) : "f"(hi), "f"(lo));
    return r;
}
__device__ __forceinline__ uint32_t smem_u32(const void* p) {
    return (uint32_t)__cvta_generic_to_shared(p);
}
__device__ __forceinline__ void cp16(uint32_t sm, const void* gm) {
    asm volatile("cp.async.cg.shared.global [%0], [%1], 16;\n" :: "r"(sm), "l"(gm));
}
__device__ __forceinline__ void ldsm4(uint32_t* r, uint32_t addr) {
    asm volatile("ldmatrix.sync.aligned.m8n8.x4.shared.b16 {%0,%1,%2,%3}, [%4];"
        : "=r"(r[0]), "=r"(r[1]), "=r"(r[2]), "=r"(r[3]) : "r"(addr));
}
__device__ __forceinline__ void mma16(float* c, const uint32_t* a, const uint32_t* b) {
    asm volatile(
        "mma.sync.aligned.m16n8k16.row.col.f32.bf16.bf16.f32 "
        "{%0,%1,%2,%3}, {%4,%5,%6,%7}, {%8,%9}, {%0,%1,%2,%3};\n"
        : "+f"(c[0]), "+f"(c[1]), "+f"(c[2]), "+f"(c[3])
        : "r"(a[0]), "r"(a[1]), "r"(a[2]), "r"(a[3]), "r"(b[0]), "r"(b[1]));
}

// ---------------- prep kernels ----------------
__device__ __forceinline__ void tconv_body(const float* src, bf16* dst,
                                           int K, int ldsrc, int coloff,
                                           int n0, int k0, int t) {
    __shared__ float sm[32][33];
    #pragma unroll
    for (int p = 0; p < 4; p++) {
        int ki = p*8 + (t >> 5);
        sm[ki][t & 31] = src[(size_t)(k0+ki)*ldsrc + coloff + n0 + (t & 31)];
    }
    __syncthreads();
    #pragma unroll
    for (int p = 0; p < 4; p++) {
        int ni = p*8 + (t >> 5);
        dst[(size_t)(n0+ni)*K + k0 + (t & 31)] = __float2bfloat16(sm[t & 31][ni]);
    }
}

// prepA: W_in (256x1024) -> WinT[1024][256]
__global__ __launch_bounds__(256) void prepA_kernel(const float* __restrict__ W_in) {
    tconv_body(W_in, g_WinT, CDIM, 1024, 0, blockIdx.x*32, blockIdx.y*32, threadIdx.x);
}

// prepB: WoutT (blocks 0..127), Wbc -> w2T rows 512..543 (blocks 128..143)
__global__ __launch_bounds__(256) void prepB_kernel(const float* __restrict__ W_out,
                                                    const float* __restrict__ W_xproj) {
    int bid = blockIdx.x, t = threadIdx.x;
    if (bid < 128) {
        tconv_body(W_out, g_WoutT, DINNER, 256, 0, (bid & 7)*32, (bid >> 3)*32, t);
    } else {
        tconv_body(W_xproj, g_w2T + (size_t)512*DINNER, DINNER, 48, 16, 0,
                   (bid - 128)*32, t);
    }
}

// wcomb: w2T[n][k] = sum_j Wdt[j][n] * Wx[k*48+j], rows 0..511; zero rows 544..639
__global__ __launch_bounds__(256) void wcomb_kernel(const float* __restrict__ Wx,
                                                    const float* __restrict__ Wdt) {
    __shared__ float s_wx[512][17];
    __shared__ float s_wd[16][8];
    const int bid = blockIdx.x, t = threadIdx.x;
    const int n8 = bid*8;
    #pragma unroll
    for (int i = 0; i < 32; i++) {
        int idx = t + i*256;
        s_wx[idx >> 4][idx & 15] = Wx[(idx >> 4)*48 + (idx & 15)];
    }
    if (t < 128) s_wd[t >> 3][t & 7] = Wdt[(t >> 3)*DINNER + n8 + (t & 7)];
    __syncthreads();
    const int w = t >> 5, lane = t & 31;
    const int n = n8 + w;
    for (int k = lane; k < DINNER; k += 32) {
        float a = 0.f;
        #pragma unroll
        for (int j = 0; j < 16; j++) a = fmaf(s_wx[k][j], s_wd[j][w], a);
        g_w2T[(size_t)n*DINNER + k] = __float2bfloat16(a);
    }
    // zero pad rows 544..639 (96*512 bf16 = 24576 u32 over 64 blocks)
    uint32_t* zp = (uint32_t*)(g_w2T + (size_t)544*DINNER);
    int i0 = bid*384 + t;
    zp[i0] = 0;
    if (t < 128) zp[i0 + 256] = 0;
}

// ---------------- LayerNorm + (B,C,H,W) -> (B,L,C) bf16 ----------------
__global__ __launch_bounds__(256) void ln_kernel(const float* __restrict__ x,
                                                 const float* __restrict__ gamma,
                                                 const float* __restrict__ beta) {
    __shared__ float sm[32*257];
    __shared__ float s_mu[32], s_rs[32];
    const int b  = blockIdx.x >> 5;
    const int l0 = (blockIdx.x & 31) * 32;
    const int t  = threadIdx.x;
    #pragma unroll
    for (int j = 0; j < 32; j++) {
        int e = j*256 + t;
        sm[(e & 31)*257 + (e >> 5)] = x[((size_t)(b*CDIM + (e >> 5)))*LSEQ + l0 + (e & 31)];
    }
    __syncthreads();
    const int w = t >> 5, lane = t & 31;
    #pragma unroll
    for (int q = 0; q < 4; q++) {
        int li = w*4 + q;
        float s = 0.f, s2 = 0.f;
        #pragma unroll
        for (int j = 0; j < 8; j++) {
            float v = sm[li*257 + lane + j*32];
            s += v; s2 = fmaf(v, v, s2);
        }
        #pragma unroll
        for (int o = 16; o; o >>= 1) {
            s  += __shfl_xor_sync(0xffffffffu, s,  o);
            s2 += __shfl_xor_sync(0xffffffffu, s2, o);
        }
        if (lane == 0) {
            float mu = s * (1.f/CDIM);
            s_mu[li] = mu;
            s_rs[li] = rsqrtf(s2 * (1.f/CDIM) - mu*mu + 1e-5f);
        }
    }
    __syncthreads();
    const float g = gamma[t], be = beta[t];
    #pragma unroll
    for (int li = 0; li < 32; li++) {
        float v = (sm[li*257 + t] - s_mu[li]) * s_rs[li];
        g_xnh[((size_t)(b*LSEQ + l0 + li))*CDIM + t] = __float2bfloat16(fmaf(v, g, be));
    }
}

// ---------------- bf16 mma.sync GEMM, 3-stage cp.async, ldmatrix frags ----------------
// BM=128, BN=128, WM=64, WN=32, 8 warps.
// MODE 1: col<512 -> u bf16 (g_uh); col>=512 -> silu -> g_gzh
// MODE 4: combined G2+G3: n0<512 -> (dt,u2) pack -> g_du; n0==512 -> bc pack (wn==0)
// MODE 5: out-fused: smem-transpose fp32 tile, out[b][c][l] = v + x  (Cf=out, e0=x)
template<int MODE>
__global__ __launch_bounds__(256) void gemm_mma(
    const bf16* __restrict__ A, const bf16* __restrict__ Bt,
    float* __restrict__ Cf, const float* __restrict__ e0,
    int K)
{
    constexpr int BM = 128, BN = 128, WM = 64, WN = 32;
    constexpr int BK = 32, ST = 3;
    constexpr int LDA = BK + 8;     // 40 bf16 rows (20 words: LDSM conflict-free)
    extern __shared__ bf16 sm[];
    bf16* As = sm;
    bf16* Bs = sm + (size_t)ST*BM*LDA;
    const int tid = threadIdx.x, wid = tid >> 5, lane = tid & 31;
    const int g = lane >> 2, q = lane & 3;
    const int wm = wid >> 2, wn = wid & 3;      // NWN = 4
    const int m0 = blockIdx.y * BM, n0 = blockIdx.x * BN;
    constexpr int MF = WM / 16, NF = WN / 8;    // 4, 4
    float acc[MF][NF][4] = {};

    auto load_stage = [&](int s, int kt) {
        const int k0 = kt * BK;
        #pragma unroll
        for (int i = 0; i < BM*4/256; i++) {
            int idx = tid + i*256;
            int r = idx >> 2, c = idx & 3;
            cp16(smem_u32(&As[(s*BM + r)*LDA + c*8]), &A[(size_t)(m0+r)*K + k0 + c*8]);
        }
        #pragma unroll
        for (int i = 0; i < BN*4/256; i++) {
            int idx = tid + i*256;
            int r = idx >> 2, c = idx & 3;
            cp16(smem_u32(&Bs[(s*BN + r)*LDA + c*8]), &Bt[(size_t)(n0+r)*K + k0 + c*8]);
        }
        asm volatile("cp.async.commit_group;\n");
    };
    auto compute = [&](int s) {
        // A frag tiles: row = wm*WM + i*16 + (lane&15), col = (lane>>4)*8 (+ h*16)
        uint32_t aB = smem_u32(As)
            + (uint32_t)(((s*BM + wm*WM + (lane & 15))*LDA + ((lane >> 4) << 3)) * 2);
        // B frag tiles: row = wn*WN + jj*16 + (lane>>4)*8 + (lane&7), col = ((lane>>3)&1)*8
        uint32_t bB = smem_u32(Bs)
            + (uint32_t)(((s*BN + wn*WN + ((lane >> 4) << 3) + (lane & 7))*LDA
                          + (((lane >> 3) & 1) << 3)) * 2);
        #pragma unroll
        for (int h = 0; h < 2; h++) {
            uint32_t af[MF][4], bfr[NF][2];
            #pragma unroll
            for (int i = 0; i < MF; i++)
                ldsm4(af[i], aB + (uint32_t)((i*16*LDA + h*16) * 2));
            #pragma unroll
            for (int jj = 0; jj < NF/2; jj++) {
                uint32_t tr[4];
                ldsm4(tr, bB + (uint32_t)((jj*16*LDA + h*16) * 2));
                bfr[2*jj][0] = tr[0]; bfr[2*jj][1] = tr[1];
                bfr[2*jj+1][0] = tr[2]; bfr[2*jj+1][1] = tr[3];
            }
            #pragma unroll
            for (int i = 0; i < MF; i++)
                #pragma unroll
                for (int j = 0; j < NF; j++)
                    mma16(acc[i][j], af[i], bfr[j]);
        }
    };

    const int nk = K / BK;
    load_stage(0, 0);
    load_stage(1, 1);
    #pragma unroll 1
    for (int kt = 0; kt < nk; kt++) {
        asm volatile("cp.async.wait_group 1;\n");
        __syncthreads();
        int nx = kt + 2;
        if (nx < nk) load_stage(nx % ST, nx);
        else asm volatile("cp.async.commit_group;\n");
        compute(kt % ST);
    }

    // ----- epilogues -----
    if (MODE == 5) {
        // transpose tile via smem, add residual, write channel-major out
        __syncthreads();
        float* smt = (float*)sm;   // 128 x 133 fp32 (alias of pipeline smem)
        #pragma unroll
        for (int i = 0; i < MF; i++) {
            int r = wm*WM + i*16 + g;
            #pragma unroll
            for (int j = 0; j < NF; j++) {
                int c = wn*WN + j*8 + 2*q;
                smt[(size_t)r*133 + c]       = acc[i][j][0];
                smt[(size_t)r*133 + c + 1]   = acc[i][j][1];
                smt[(size_t)(r+8)*133 + c]   = acc[i][j][2];
                smt[(size_t)(r+8)*133 + c+1] = acc[i][j][3];
            }
        }
        __syncthreads();
        const int b = m0 >> 10, l0 = m0 & 1023;
        #pragma unroll 4
        for (int i = 0; i < 64; i++) {
            int idx = tid + i*256;
            int c = idx >> 7, l = idx & 127;
            size_t oi = ((size_t)(b*CDIM + n0 + c))*LSEQ + l0 + l;
            Cf[oi] = smt[(size_t)l*133 + c] + e0[oi];
        }
        return;
    }
    #pragma unroll
    for (int i = 0; i < MF; i++) {
        int row = m0 + wm*WM + i*16 + g;
        if (MODE == 1) {
            #pragma unroll
            for (int j = 0; j < NF; j++) {
                int col = n0 + wn*WN + j*8 + 2*q;
                float v0 = acc[i][j][0], v1 = acc[i][j][1];
                float v2 = acc[i][j][2], v3 = acc[i][j][3];
                if (col < DINNER) {
                    *(uint32_t*)&g_uh[(size_t)(row  )*DINNER + col] = pbf2(v0, v1);
                    *(uint32_t*)&g_uh[(size_t)(row+8)*DINNER + col] = pbf2(v2, v3);
                } else {
                    int cz = col - DINNER;
                    *(uint32_t*)&g_gzh[(size_t)(row  )*DINNER + cz] =
                        pbf2(siluf(v0), siluf(v1));
                    *(uint32_t*)&g_gzh[(size_t)(row+8)*DINNER + cz] =
                        pbf2(siluf(v2), siluf(v3));
                }
            }
        } else if (MODE == 4) {
            if (n0 < DINNER) {
                #pragma unroll
                for (int j = 0; j < NF; j++) {
                    int col = n0 + wn*WN + j*8 + 2*q;
                    float v0 = acc[i][j][0], v1 = acc[i][j][1];
                    float v2 = acc[i][j][2], v3 = acc[i][j][3];
                    float b0 = e0[col], b1 = e0[col+1];
                    uint32_t ua = *(const uint32_t*)&g_u2h[(size_t)(row  )*DINNER + col];
                    uint32_t ub = *(const uint32_t*)&g_u2h[(size_t)(row+8)*DINNER + col];
                    uint32_t d0 = (uint32_t)__bfloat16_as_ushort(__float2bfloat16(softplusf(v0 + b0)));
                    uint32_t d1 = (uint32_t)__bfloat16_as_ushort(__float2bfloat16(softplusf(v1 + b1)));
                    uint32_t d2 = (uint32_t)__bfloat16_as_ushort(__float2bfloat16(softplusf(v2 + b0)));
                    uint32_t d3 = (uint32_t)__bfloat16_as_ushort(__float2bfloat16(softplusf(v3 + b1)));
                    uint2 wa = make_uint2(d0 | ((ua & 0xFFFFu) << 16), d1 | (ua & 0xFFFF0000u));
                    uint2 wb = make_uint2(d2 | ((ub & 0xFFFFu) << 16), d3 | (ub & 0xFFFF0000u));
                    *(uint2*)&g_du[(size_t)(row  )*DINNER + col] = wa;
                    *(uint2*)&g_du[(size_t)(row+8)*DINNER + col] = wb;
                }
            } else if (wn == 0) {
                // bc pack: cols n0..n0+31 -> (B_s, C_s), s = col - n0 (pair s, s+16)
                #pragma unroll
                for (int j = 0; j < 2; j++) {
                    int s = j*8 + 2*q;
                    float4 lo = make_float4(acc[i][j][0], acc[i][j+2][0],
                                            acc[i][j][1], acc[i][j+2][1]);
                    float4 hi = make_float4(acc[i][j][2], acc[i][j+2][2],
                                            acc[i][j][3], acc[i][j+2][3]);
                    *(float4*)&g_bc[(size_t)(row  )*DSTATE + s] = lo;
                    *(float4*)&g_bc[(size_t)(row+8)*DSTATE + s] = hi;
                }
            }
        }
    }
}

// ---------------- depthwise causal conv (D_CONV=4) + SiLU, bf162 ----------------
__global__ __launch_bounds__(256) void conv_silu_kernel(const float* __restrict__ cw,
                                                        const float* __restrict__ cb) {
    int gid = blockIdx.x*256 + threadIdx.x;
    int d2  = gid & 255;
    int row = gid >> 8;
    int l   = row & (LSEQ-1);
    int d   = d2 * 2;
    float a0 = cb[d], a1 = cb[d+1];
    const uint32_t* up = (const uint32_t*)g_uh;
    #pragma unroll
    for (int k = 0; k < 4; k++) {
        int ll = l - 3 + k;
        if (ll >= 0) {
            uint32_t w = up[(size_t)(row - 3 + k)*256 + d2];
            bf162 p = *(bf162*)&w;
            a0 = fmaf(__bfloat162float(p.x), cw[d*4 + k],     a0);
            a1 = fmaf(__bfloat162float(p.y), cw[(d+1)*4 + k], a1);
        }
    }
    ((uint32_t*)g_u2h)[gid] = pbf2(siluf(a0), siluf(a1));
}

// ---------------- selective scan: row-major smem-tiled, prefetch (verified R9) ------
__global__ __launch_bounds__(256) void scan_kernel(const float* __restrict__ A_log,
                                                   const float* __restrict__ D_skip) {
    __shared__ uint32_t       s_du[16][16];
    __shared__ float2         s_bc[16][16];
    __shared__ unsigned short s_gz[16][16];
    __shared__ unsigned short s_yg[16][16];
    const int b    = blockIdx.x >> 5;
    const int dblk = (blockIdx.x & 31) * 16;
    const int tid  = threadIdx.x;
    const int widx = tid >> 5, lane = tid & 31;
    const int half = lane >> 4, s = lane & 15;
    const int ch   = 2*widx + half;
    const int d    = dblk + ch;
    const float Aval = -__expf(A_log[d*DSTATE + s]);
    const float Dd   = D_skip[d];
    const size_t rb  = (size_t)b * LSEQ;
    const int li = tid >> 4, dd = tid & 15;
    const uint32_t*       duG = g_du;
    const unsigned short* gzG = (const unsigned short*)g_gzh;
    unsigned short*       ygG = (unsigned short*)g_ygh;

    uint32_t r_du; unsigned short r_gz; float2 r_bc;
    auto ldchunk = [&](int c0) {
        size_t rw = (rb + c0 + li);
        r_du = duG[rw*DINNER + dblk + dd];
        r_gz = gzG[rw*DINNER + dblk + dd];
        r_bc = g_bc[rw*DSTATE + dd];
    };
    float h = 0.f;
    ldchunk(0);
    #pragma unroll 1
    for (int c0 = 0; c0 < LSEQ; c0 += 16) {
        __syncthreads();
        s_du[li][dd] = r_du;
        s_gz[li][dd] = r_gz;
        s_bc[li][dd] = r_bc;
        __syncthreads();
        if (c0 + 16 < LSEQ) ldchunk(c0 + 16);
        #pragma unroll
        for (int j = 0; j < 16; j++) {
            uint32_t w = s_du[j][ch];
            bf162 p = *(bf162*)&w;
            float dt = __bfloat162float(p.x);
            float u2 = __bfloat162float(p.y);
            float2 bcv = s_bc[j][s];
            float dA = __expf(dt * Aval);
            h = fmaf(dA, h, dt * u2 * bcv.x);
            float pr = h * bcv.y;
            pr += __shfl_xor_sync(0xffffffffu, pr, 8);
            pr += __shfl_xor_sync(0xffffffffu, pr, 4);
            pr += __shfl_xor_sync(0xffffffffu, pr, 2);
            pr += __shfl_xor_sync(0xffffffffu, pr, 1);
            if (s == j) {
                float yv = pr + u2 * Dd;
                float gzf = __bfloat162float(__ushort_as_bfloat16(s_gz[j][ch]));
                s_yg[j][ch] = __bfloat16_as_ushort(__float2bfloat16(yv * gzf));
            }
        }
        __syncthreads();
        ygG[(rb + c0 + li)*DINNER + dblk + dd] = s_yg[li][dd];
    }
}

// ---------------- host launch ----------------
extern "C" void kernel_launch(void* const* d_in, const int* in_sizes, int n_in,
                              void* d_out, int out_size) {
    const float* x       = (const float*)d_in[0];
    const float* ln_g    = (const float*)d_in[1];
    const float* ln_b    = (const float*)d_in[2];
    const float* W_in    = (const float*)d_in[3];
    const float* conv_w  = (const float*)d_in[4];
    const float* conv_b  = (const float*)d_in[5];
    const float* W_xproj = (const float*)d_in[6];
    const float* W_dt    = (const float*)d_in[7];
    const float* b_dt    = (const float*)d_in[8];
    const float* A_log   = (const float*)d_in[9];
    const float* D_skip  = (const float*)d_in[10];
    const float* W_out   = (const float*)d_in[11];
    float* out = (float*)d_out;

    bf16 *p_xnh, *p_u2h, *p_ygh, *p_WinT, *p_w2T, *p_WoutT;
    cudaGetSymbolAddress((void**)&p_xnh,   g_xnh);
    cudaGetSymbolAddress((void**)&p_u2h,   g_u2h);
    cudaGetSymbolAddress((void**)&p_ygh,   g_ygh);
    cudaGetSymbolAddress((void**)&p_WinT,  g_WinT);
    cudaGetSymbolAddress((void**)&p_w2T,   g_w2T);
    cudaGetSymbolAddress((void**)&p_WoutT, g_WoutT);

    const int SMB = 3*(128+128)*40*2;          // 61440 pipeline
    const int SMO = 128*133*4;                 // 68096 (>= SMB) for MODE 5
    cudaFuncSetAttribute(gemm_mma<1>, cudaFuncAttributeMaxDynamicSharedMemorySize, SMB);
    cudaFuncSetAttribute(gemm_mma<4>, cudaFuncAttributeMaxDynamicSharedMemorySize, SMB);
    cudaFuncSetAttribute(gemm_mma<5>, cudaFuncAttributeMaxDynamicSharedMemorySize, SMO);

    // launch index (ncu captures index 3 = G1):
    ln_kernel<<<BATCH*32, 256>>>(x, ln_g, ln_b);                       // 0
    prepA_kernel<<<dim3(32, 8), 256>>>(W_in);                          // 1
    prepB_kernel<<<144, 256>>>(W_out, W_xproj);                        // 2
    // G1: xn @ W_in (8192 x 1024 x 256) -> u bf16 / silu(z) bf16
    gemm_mma<1><<<dim3(8, 64), 256, SMB>>>(                            // 3
        p_xnh, p_WinT, nullptr, nullptr, CDIM);
    wcomb_kernel<<<64, 256>>>(W_xproj, W_dt);                          // 4
    conv_silu_kernel<<<NROWS, 256>>>(conv_w, conv_b);                  // 5
    // G2+G3: u2 @ w2T (8192 x 544(pad640) x 512) -> (dt,u2) + (B,C)
    gemm_mma<4><<<dim3(5, 64), 256, SMB>>>(                            // 6
        p_u2h, p_w2T, nullptr, b_dt, DINNER);
    scan_kernel<<<256, 256>>>(A_log, D_skip);                          // 7
    // G4 fused: yg @ W_out + transpose + residual -> out
    gemm_mma<5><<<dim3(2, 64), 256, SMO>>>(                            // 8
        p_ygh, p_WoutT, out, x, DINNER);
}

// round 11
// speedup vs baseline: 1.2992x; 1.2992x over previous
#include <cuda_runtime.h>
#include <cuda_bf16.h>
#include <math.h>
#include <stdint.h>

// ---------------- problem constants ----------------
#define LSEQ   1024
#define BATCH  8
#define CDIM   256
#define DINNER 512
#define DSTATE 16
#define NROWS  (BATCH*LSEQ)   // 8192

typedef __nv_bfloat16 bf16;
typedef __nv_bfloat162 bf162;

// ---------------- scratch (static, no allocs) ----------------
__device__ __align__(256) bf16     g_xnh  [(size_t)NROWS*CDIM];
__device__ __align__(256) bf16     g_uh   [(size_t)NROWS*DINNER];
__device__ __align__(256) bf16     g_gzh  [(size_t)NROWS*DINNER];   // silu(z), [row][d]
__device__ __align__(256) bf16     g_u2h  [(size_t)NROWS*DINNER];
__device__ __align__(256) uint32_t g_du   [(size_t)NROWS*DINNER];   // (dt,u2) pack, [row][d]
__device__ __align__(256) float2   g_bc   [(size_t)NROWS*DSTATE];   // [row][s]
__device__ __align__(256) bf16     g_ygh  [(size_t)NROWS*DINNER];   // [row][d]
// weights, bf16, K-major [N][K]
__device__ __align__(256) bf16     g_WinT  [(size_t)1024*CDIM];
__device__ __align__(256) bf16     g_w2T   [(size_t)640*DINNER];    // [0:512)=wcomb, [512:544)=Wbc, rest 0
__device__ __align__(256) bf16     g_WoutT [(size_t)CDIM*DINNER];

// ---------------- small helpers ----------------
__device__ __forceinline__ float siluf(float v) { return v / (1.f + __expf(-v)); }
__device__ __forceinline__ float softplusf(float v) {
    return (v > 20.f) ? v : log1pf(__expf(v));
}
__device__ __forceinline__ uint32_t pbf2(float lo, float hi) {
    uint32_t r;
    asm("cvt.rn.bf16x2.f32 %0, %1, %2;" : "=r"(r) : "f"(hi), "f"(lo));
    return r;
}
__device__ __forceinline__ uint32_t smem_u32(const void* p) {
    return (uint32_t)__cvta_generic_to_shared(p);
}
__device__ __forceinline__ void cp16(uint32_t sm, const void* gm) {
    asm volatile("cp.async.cg.shared.global [%0], [%1], 16;\n" :: "r"(sm), "l"(gm));
}
__device__ __forceinline__ void ldsm4(uint32_t* r, uint32_t addr) {
    asm volatile("ldmatrix.sync.aligned.m8n8.x4.shared.b16 {%0,%1,%2,%3}, [%4];"
        : "=r"(r[0]), "=r"(r[1]), "=r"(r[2]), "=r"(r[3]) : "r"(addr));
}
__device__ __forceinline__ void mma16(float* c, const uint32_t* a, const uint32_t* b) {
    asm volatile(
        "mma.sync.aligned.m16n8k16.row.col.f32.bf16.bf16.f32 "
        "{%0,%1,%2,%3}, {%4,%5,%6,%7}, {%8,%9}, {%0,%1,%2,%3};\n"
        : "+f"(c[0]), "+f"(c[1]), "+f"(c[2]), "+f"(c[3])
        : "r"(a[0]), "r"(a[1]), "r"(a[2]), "r"(a[3]), "r"(b[0]), "r"(b[1]));
}

// ---------------- prep kernels ----------------
__device__ __forceinline__ void tconv_body(const float* src, bf16* dst,
                                           int K, int ldsrc, int coloff,
                                           int n0, int k0, int t) {
    __shared__ float sm[32][33];
    #pragma unroll
    for (int p = 0; p < 4; p++) {
        int ki = p*8 + (t >> 5);
        sm[ki][t & 31] = src[(size_t)(k0+ki)*ldsrc + coloff + n0 + (t & 31)];
    }
    __syncthreads();
    #pragma unroll
    for (int p = 0; p < 4; p++) {
        int ni = p*8 + (t >> 5);
        dst[(size_t)(n0+ni)*K + k0 + (t & 31)] = __float2bfloat16(sm[t & 31][ni]);
    }
}

// prepA: W_in (256x1024) -> WinT[1024][256]
__global__ __launch_bounds__(256) void prepA_kernel(const float* __restrict__ W_in) {
    tconv_body(W_in, g_WinT, CDIM, 1024, 0, blockIdx.x*32, blockIdx.y*32, threadIdx.x);
}

// prepB: WoutT (blocks 0..127), Wbc -> w2T rows 512..543 (blocks 128..143)
__global__ __launch_bounds__(256) void prepB_kernel(const float* __restrict__ W_out,
                                                    const float* __restrict__ W_xproj) {
    int bid = blockIdx.x, t = threadIdx.x;
    if (bid < 128) {
        tconv_body(W_out, g_WoutT, DINNER, 256, 0, (bid & 7)*32, (bid >> 3)*32, t);
    } else {
        tconv_body(W_xproj, g_w2T + (size_t)512*DINNER, DINNER, 48, 16, 0,
                   (bid - 128)*32, t);
    }
}

// wcomb: w2T[n][k] = sum_j Wdt[j][n] * Wx[k*48+j], rows 0..511; zero rows 544..639
__global__ __launch_bounds__(256) void wcomb_kernel(const float* __restrict__ Wx,
                                                    const float* __restrict__ Wdt) {
    __shared__ float s_wx[512][17];
    __shared__ float s_wd[16][8];
    const int bid = blockIdx.x, t = threadIdx.x;
    const int n8 = bid*8;
    #pragma unroll
    for (int i = 0; i < 32; i++) {
        int idx = t + i*256;
        s_wx[idx >> 4][idx & 15] = Wx[(idx >> 4)*48 + (idx & 15)];
    }
    if (t < 128) s_wd[t >> 3][t & 7] = Wdt[(t >> 3)*DINNER + n8 + (t & 7)];
    __syncthreads();
    const int w = t >> 5, lane = t & 31;
    const int n = n8 + w;
    for (int k = lane; k < DINNER; k += 32) {
        float a = 0.f;
        #pragma unroll
        for (int j = 0; j < 16; j++) a = fmaf(s_wx[k][j], s_wd[j][w], a);
        g_w2T[(size_t)n*DINNER + k] = __float2bfloat16(a);
    }
    uint32_t* zp = (uint32_t*)(g_w2T + (size_t)544*DINNER);
    int i0 = bid*384 + t;
    zp[i0] = 0;
    if (t < 128) zp[i0 + 256] = 0;
}

// ---------------- LayerNorm + (B,C,H,W) -> (B,L,C) bf16 ----------------
__global__ __launch_bounds__(256) void ln_kernel(const float* __restrict__ x,
                                                 const float* __restrict__ gamma,
                                                 const float* __restrict__ beta) {
    __shared__ float sm[32*257];
    __shared__ float s_mu[32], s_rs[32];
    const int b  = blockIdx.x >> 5;
    const int l0 = (blockIdx.x & 31) * 32;
    const int t  = threadIdx.x;
    #pragma unroll
    for (int j = 0; j < 32; j++) {
        int e = j*256 + t;
        sm[(e & 31)*257 + (e >> 5)] = x[((size_t)(b*CDIM + (e >> 5)))*LSEQ + l0 + (e & 31)];
    }
    __syncthreads();
    const int w = t >> 5, lane = t & 31;
    #pragma unroll
    for (int q = 0; q < 4; q++) {
        int li = w*4 + q;
        float s = 0.f, s2 = 0.f;
        #pragma unroll
        for (int j = 0; j < 8; j++) {
            float v = sm[li*257 + lane + j*32];
            s += v; s2 = fmaf(v, v, s2);
        }
        #pragma unroll
        for (int o = 16; o; o >>= 1) {
            s  += __shfl_xor_sync(0xffffffffu, s,  o);
            s2 += __shfl_xor_sync(0xffffffffu, s2, o);
        }
        if (lane == 0) {
            float mu = s * (1.f/CDIM);
            s_mu[li] = mu;
            s_rs[li] = rsqrtf(s2 * (1.f/CDIM) - mu*mu + 1e-5f);
        }
    }
    __syncthreads();
    const float g = gamma[t], be = beta[t];
    #pragma unroll
    for (int li = 0; li < 32; li++) {
        float v = (sm[li*257 + t] - s_mu[li]) * s_rs[li];
        g_xnh[((size_t)(b*LSEQ + l0 + li))*CDIM + t] = __float2bfloat16(fmaf(v, g, be));
    }
}

// ---------------- bf16 mma.sync GEMM, 3-stage cp.async, ldmatrix frags ----------------
// BM=128, BN=128, WM=64, WN=32, 8 warps.
// MODE 1: col<512 -> u bf16 (g_uh); col>=512 -> silu -> g_gzh
// MODE 4: combined G2+G3: n0<512 -> (dt,u2) pack -> g_du; n0==512 -> bc pack (wn==0)
// MODE 5: out-fused: smem-transpose fp32 tile, out[b][c][l] = v + x  (Cf=out, e0=x)
template<int MODE>
__global__ __launch_bounds__(256) void gemm_mma(
    const bf16* __restrict__ A, const bf16* __restrict__ Bt,
    float* __restrict__ Cf, const float* __restrict__ e0,
    int K)
{
    constexpr int BM = 128, BN = 128, WM = 64, WN = 32;
    constexpr int BK = 32, ST = 3;
    constexpr int LDA = BK + 8;
    extern __shared__ bf16 sm[];
    bf16* As = sm;
    bf16* Bs = sm + (size_t)ST*BM*LDA;
    const int tid = threadIdx.x, wid = tid >> 5, lane = tid & 31;
    const int g = lane >> 2, q = lane & 3;
    const int wm = wid >> 2, wn = wid & 3;
    const int m0 = blockIdx.y * BM, n0 = blockIdx.x * BN;
    constexpr int MF = WM / 16, NF = WN / 8;
    float acc[MF][NF][4] = {};

    auto load_stage = [&](int s, int kt) {
        const int k0 = kt * BK;
        #pragma unroll
        for (int i = 0; i < BM*4/256; i++) {
            int idx = tid + i*256;
            int r = idx >> 2, c = idx & 3;
            cp16(smem_u32(&As[(s*BM + r)*LDA + c*8]), &A[(size_t)(m0+r)*K + k0 + c*8]);
        }
        #pragma unroll
        for (int i = 0; i < BN*4/256; i++) {
            int idx = tid + i*256;
            int r = idx >> 2, c = idx & 3;
            cp16(smem_u32(&Bs[(s*BN + r)*LDA + c*8]), &Bt[(size_t)(n0+r)*K + k0 + c*8]);
        }
        asm volatile("cp.async.commit_group;\n");
    };
    auto compute = [&](int s) {
        uint32_t aB = smem_u32(As)
            + (uint32_t)(((s*BM + wm*WM + (lane & 15))*LDA + ((lane >> 4) << 3)) * 2);
        uint32_t bB = smem_u32(Bs)
            + (uint32_t)(((s*BN + wn*WN + ((lane >> 4) << 3) + (lane & 7))*LDA
                          + (((lane >> 3) & 1) << 3)) * 2);
        #pragma unroll
        for (int h = 0; h < 2; h++) {
            uint32_t af[MF][4], bfr[NF][2];
            #pragma unroll
            for (int i = 0; i < MF; i++)
                ldsm4(af[i], aB + (uint32_t)((i*16*LDA + h*16) * 2));
            #pragma unroll
            for (int jj = 0; jj < NF/2; jj++) {
                uint32_t tr[4];
                ldsm4(tr, bB + (uint32_t)((jj*16*LDA + h*16) * 2));
                bfr[2*jj][0] = tr[0]; bfr[2*jj][1] = tr[1];
                bfr[2*jj+1][0] = tr[2]; bfr[2*jj+1][1] = tr[3];
            }
            #pragma unroll
            for (int i = 0; i < MF; i++)
                #pragma unroll
                for (int j = 0; j < NF; j++)
                    mma16(acc[i][j], af[i], bfr[j]);
        }
    };

    const int nk = K / BK;
    load_stage(0, 0);
    load_stage(1, 1);
    #pragma unroll 1
    for (int kt = 0; kt < nk; kt++) {
        asm volatile("cp.async.wait_group 1;\n");
        __syncthreads();
        int nx = kt + 2;
        if (nx < nk) load_stage(nx % ST, nx);
        else asm volatile("cp.async.commit_group;\n");
        compute(kt % ST);
    }

    // ----- epilogues -----
    if (MODE == 5) {
        __syncthreads();
        float* smt = (float*)sm;   // 128 x 133 fp32
        #pragma unroll
        for (int i = 0; i < MF; i++) {
            int r = wm*WM + i*16 + g;
            #pragma unroll
            for (int j = 0; j < NF; j++) {
                int c = wn*WN + j*8 + 2*q;
                smt[(size_t)r*133 + c]       = acc[i][j][0];
                smt[(size_t)r*133 + c + 1]   = acc[i][j][1];
                smt[(size_t)(r+8)*133 + c]   = acc[i][j][2];
                smt[(size_t)(r+8)*133 + c+1] = acc[i][j][3];
            }
        }
        __syncthreads();
        const int b = m0 >> 10, l0 = m0 & 1023;
        #pragma unroll 4
        for (int i = 0; i < 64; i++) {
            int idx = tid + i*256;
            int c = idx >> 7, l = idx & 127;
            size_t oi = ((size_t)(b*CDIM + n0 + c))*LSEQ + l0 + l;
            Cf[oi] = smt[(size_t)l*133 + c] + e0[oi];
        }
        return;
    }
    #pragma unroll
    for (int i = 0; i < MF; i++) {
        int row = m0 + wm*WM + i*16 + g;
        if (MODE == 1) {
            #pragma unroll
            for (int j = 0; j < NF; j++) {
                int col = n0 + wn*WN + j*8 + 2*q;
                float v0 = acc[i][j][0], v1 = acc[i][j][1];
                float v2 = acc[i][j][2], v3 = acc[i][j][3];
                if (col < DINNER) {
                    *(uint32_t*)&g_uh[(size_t)(row  )*DINNER + col] = pbf2(v0, v1);
                    *(uint32_t*)&g_uh[(size_t)(row+8)*DINNER + col] = pbf2(v2, v3);
                } else {
                    int cz = col - DINNER;
                    *(uint32_t*)&g_gzh[(size_t)(row  )*DINNER + cz] =
                        pbf2(siluf(v0), siluf(v1));
                    *(uint32_t*)&g_gzh[(size_t)(row+8)*DINNER + cz] =
                        pbf2(siluf(v2), siluf(v3));
                }
            }
        } else if (MODE == 4) {
            if (n0 < DINNER) {
                #pragma unroll
                for (int j = 0; j < NF; j++) {
                    int col = n0 + wn*WN + j*8 + 2*q;
                    float v0 = acc[i][j][0], v1 = acc[i][j][1];
                    float v2 = acc[i][j][2], v3 = acc[i][j][3];
                    float b0 = e0[col], b1 = e0[col+1];
                    uint32_t ua = *(const uint32_t*)&g_u2h[(size_t)(row  )*DINNER + col];
                    uint32_t ub = *(const uint32_t*)&g_u2h[(size_t)(row+8)*DINNER + col];
                    uint32_t d0 = (uint32_t)__bfloat16_as_ushort(__float2bfloat16(softplusf(v0 + b0)));
                    uint32_t d1 = (uint32_t)__bfloat16_as_ushort(__float2bfloat16(softplusf(v1 + b1)));
                    uint32_t d2 = (uint32_t)__bfloat16_as_ushort(__float2bfloat16(softplusf(v2 + b0)));
                    uint32_t d3 = (uint32_t)__bfloat16_as_ushort(__float2bfloat16(softplusf(v3 + b1)));
                    uint2 wa = make_uint2(d0 | ((ua & 0xFFFFu) << 16), d1 | (ua & 0xFFFF0000u));
                    uint2 wb = make_uint2(d2 | ((ub & 0xFFFFu) << 16), d3 | (ub & 0xFFFF0000u));
                    *(uint2*)&g_du[(size_t)(row  )*DINNER + col] = wa;
                    *(uint2*)&g_du[(size_t)(row+8)*DINNER + col] = wb;
                }
            } else if (wn == 0) {
                #pragma unroll
                for (int j = 0; j < 2; j++) {
                    int s = j*8 + 2*q;
                    float4 lo = make_float4(acc[i][j][0], acc[i][j+2][0],
                                            acc[i][j][1], acc[i][j+2][1]);
                    float4 hi = make_float4(acc[i][j][2], acc[i][j+2][2],
                                            acc[i][j][3], acc[i][j+2][3]);
                    *(float4*)&g_bc[(size_t)(row  )*DSTATE + s] = lo;
                    *(float4*)&g_bc[(size_t)(row+8)*DSTATE + s] = hi;
                }
            }
        }
    }
}

// ---------------- depthwise causal conv (D_CONV=4) + SiLU, bf162 ----------------
__global__ __launch_bounds__(256) void conv_silu_kernel(const float* __restrict__ cw,
                                                        const float* __restrict__ cb) {
    int gid = blockIdx.x*256 + threadIdx.x;
    int d2  = gid & 255;
    int row = gid >> 8;
    int l   = row & (LSEQ-1);
    int d   = d2 * 2;
    float a0 = cb[d], a1 = cb[d+1];
    const uint32_t* up = (const uint32_t*)g_uh;
    #pragma unroll
    for (int k = 0; k < 4; k++) {
        int ll = l - 3 + k;
        if (ll >= 0) {
            uint32_t w = up[(size_t)(row - 3 + k)*256 + d2];
            bf162 p = *(bf162*)&w;
            a0 = fmaf(__bfloat162float(p.x), cw[d*4 + k],     a0);
            a1 = fmaf(__bfloat162float(p.y), cw[(d+1)*4 + k], a1);
        }
    }
    ((uint32_t*)g_u2h)[gid] = pbf2(siluf(a0), siluf(a1));
}

// ---------------- selective scan v4: phase-split for ILP ----------------
// Same tiling as verified R9 scan; the 16-step inner loop is split into
// (A) recurrence-only (h-chain + p[j] products), (B) 16 concurrent butterfly
// reductions, (C) lane s writes step j=s. Identical arithmetic & add order.
__global__ __launch_bounds__(256) void scan_kernel(const float* __restrict__ A_log,
                                                   const float* __restrict__ D_skip) {
    __shared__ uint32_t       s_du[16][16];
    __shared__ float2         s_bc[16][16];
    __shared__ unsigned short s_gz[16][16];
    __shared__ unsigned short s_yg[16][16];
    const int b    = blockIdx.x >> 5;
    const int dblk = (blockIdx.x & 31) * 16;
    const int tid  = threadIdx.x;
    const int widx = tid >> 5, lane = tid & 31;
    const int half = lane >> 4, s = lane & 15;
    const int ch   = 2*widx + half;
    const int d    = dblk + ch;
    const float Aval = -__expf(A_log[d*DSTATE + s]);
    const float Dd   = D_skip[d];
    const size_t rb  = (size_t)b * LSEQ;
    const int li = tid >> 4, dd = tid & 15;
    const uint32_t*       duG = g_du;
    const unsigned short* gzG = (const unsigned short*)g_gzh;
    unsigned short*       ygG = (unsigned short*)g_ygh;

    uint32_t r_du; unsigned short r_gz; float2 r_bc;
    auto ldchunk = [&](int c0) {
        size_t rw = (rb + c0 + li);
        r_du = duG[rw*DINNER + dblk + dd];
        r_gz = gzG[rw*DINNER + dblk + dd];
        r_bc = g_bc[rw*DSTATE + dd];
    };
    float h = 0.f;
    ldchunk(0);
    #pragma unroll 1
    for (int c0 = 0; c0 < LSEQ; c0 += 16) {
        __syncthreads();
        s_du[li][dd] = r_du;
        s_gz[li][dd] = r_gz;
        s_bc[li][dd] = r_bc;
        __syncthreads();
        if (c0 + 16 < LSEQ) ldchunk(c0 + 16);
        // Phase A: recurrence, all loads/exps independent -> ILP
        float p[16];
        #pragma unroll
        for (int j = 0; j < 16; j++) {
            uint32_t w = s_du[j][ch];
            bf162 pk = *(bf162*)&w;
            float dt = __bfloat162float(pk.x);
            float u2 = __bfloat162float(pk.y);
            float2 bcv = s_bc[j][s];
            float dA = __expf(dt * Aval);
            h = fmaf(dA, h, dt * u2 * bcv.x);
            p[j] = h * bcv.y;
        }
        // Phase B: 16 independent butterfly chains per round -> latency hidden
        #pragma unroll
        for (int o = 8; o; o >>= 1) {
            #pragma unroll
            for (int j = 0; j < 16; j++)
                p[j] += __shfl_xor_sync(0xffffffffu, p[j], o);
        }
        // Phase C: lane s finalizes step j = s for its channel
        {
            uint32_t w = s_du[s][ch];
            bf162 pk = *(bf162*)&w;
            float u2 = __bfloat162float(pk.y);
            float yv = p[s] + u2 * Dd;
            float gzf = __bfloat162float(__ushort_as_bfloat16(s_gz[s][ch]));
            s_yg[s][ch] = __bfloat16_as_ushort(__float2bfloat16(yv * gzf));
        }
        __syncthreads();
        ygG[(rb + c0 + li)*DINNER + dblk + dd] = s_yg[li][dd];
    }
}

// ---------------- host launch ----------------
extern "C" void kernel_launch(void* const* d_in, const int* in_sizes, int n_in,
                              void* d_out, int out_size) {
    const float* x       = (const float*)d_in[0];
    const float* ln_g    = (const float*)d_in[1];
    const float* ln_b    = (const float*)d_in[2];
    const float* W_in    = (const float*)d_in[3];
    const float* conv_w  = (const float*)d_in[4];
    const float* conv_b  = (const float*)d_in[5];
    const float* W_xproj = (const float*)d_in[6];
    const float* W_dt    = (const float*)d_in[7];
    const float* b_dt    = (const float*)d_in[8];
    const float* A_log   = (const float*)d_in[9];
    const float* D_skip  = (const float*)d_in[10];
    const float* W_out   = (const float*)d_in[11];
    float* out = (float*)d_out;

    bf16 *p_xnh, *p_u2h, *p_ygh, *p_WinT, *p_w2T, *p_WoutT;
    cudaGetSymbolAddress((void**)&p_xnh,   g_xnh);
    cudaGetSymbolAddress((void**)&p_u2h,   g_u2h);
    cudaGetSymbolAddress((void**)&p_ygh,   g_ygh);
    cudaGetSymbolAddress((void**)&p_WinT,  g_WinT);
    cudaGetSymbolAddress((void**)&p_w2T,   g_w2T);
    cudaGetSymbolAddress((void**)&p_WoutT, g_WoutT);

    const int SMB = 3*(128+128)*40*2;          // 61440 pipeline
    const int SMO = 128*133*4;                 // 68096 for MODE 5
    cudaFuncSetAttribute(gemm_mma<1>, cudaFuncAttributeMaxDynamicSharedMemorySize, SMB);
    cudaFuncSetAttribute(gemm_mma<4>, cudaFuncAttributeMaxDynamicSharedMemorySize, SMB);
    cudaFuncSetAttribute(gemm_mma<5>, cudaFuncAttributeMaxDynamicSharedMemorySize, SMO);

    // launch index (ncu captures index 3 = G1):
    ln_kernel<<<BATCH*32, 256>>>(x, ln_g, ln_b);                       // 0
    prepA_kernel<<<dim3(32, 8), 256>>>(W_in);                          // 1
    prepB_kernel<<<144, 256>>>(W_out, W_xproj);                        // 2
    gemm_mma<1><<<dim3(8, 64), 256, SMB>>>(                            // 3  G1
        p_xnh, p_WinT, nullptr, nullptr, CDIM);
    wcomb_kernel<<<64, 256>>>(W_xproj, W_dt);                          // 4
    conv_silu_kernel<<<NROWS, 256>>>(conv_w, conv_b);                  // 5
    gemm_mma<4><<<dim3(5, 64), 256, SMB>>>(                            // 6  G2+G3
        p_u2h, p_w2T, nullptr, b_dt, DINNER);
    scan_kernel<<<256, 256>>>(A_log, D_skip);                          // 7
    gemm_mma<5><<<dim3(2, 64), 256, SMO>>>(                            // 8  G4+out
        p_ygh, p_WoutT, out, x, DINNER);
}

// round 12
// speedup vs baseline: 1.3484x; 1.0379x over previous
#include <cuda_runtime.h>
#include <cuda_bf16.h>
#include <math.h>
#include <stdint.h>

// ---------------- problem constants ----------------
#define LSEQ   1024
#define BATCH  8
#define CDIM   256
#define DINNER 512
#define DSTATE 16
#define NROWS  (BATCH*LSEQ)   // 8192

typedef __nv_bfloat16 bf16;
typedef __nv_bfloat162 bf162;

// ---------------- scratch (static, no allocs) ----------------
__device__ __align__(256) bf16     g_xnh  [(size_t)NROWS*CDIM];
__device__ __align__(256) bf16     g_uh   [(size_t)NROWS*DINNER];
__device__ __align__(256) bf16     g_gzh  [(size_t)NROWS*DINNER];   // silu(z), [row][d]
__device__ __align__(256) bf16     g_u2h  [(size_t)NROWS*DINNER];
__device__ __align__(256) uint32_t g_du   [(size_t)NROWS*DINNER];   // (dt,u2) pack, [row][d]
__device__ __align__(256) float2   g_bc   [(size_t)NROWS*DSTATE];   // [row][s]
__device__ __align__(256) bf16     g_ygh  [(size_t)NROWS*DINNER];   // [row][d]
// weights, bf16, K-major [N][K]
__device__ __align__(256) bf16     g_WinT  [(size_t)1024*CDIM];
__device__ __align__(256) bf16     g_w2T   [(size_t)640*DINNER];    // [0:512)=wcomb, [512:544)=Wbc, rest 0
__device__ __align__(256) bf16     g_WoutT [(size_t)CDIM*DINNER];

// ---------------- small helpers ----------------
__device__ __forceinline__ float siluf(float v) { return v / (1.f + __expf(-v)); }
__device__ __forceinline__ float softplusf(float v) {
    return (v > 20.f) ? v : log1pf(__expf(v));
}
__device__ __forceinline__ uint32_t pbf2(float lo, float hi) {
    uint32_t r;
    asm("cvt.rn.bf16x2.f32 %0, %1, %2;" : "=r"(r) : "f"(hi), "f"(lo));
    return r;
}
__device__ __forceinline__ uint32_t smem_u32(const void* p) {
    return (uint32_t)__cvta_generic_to_shared(p);
}
__device__ __forceinline__ void cp16(uint32_t sm, const void* gm) {
    asm volatile("cp.async.cg.shared.global [%0], [%1], 16;\n" :: "r"(sm), "l"(gm));
}
__device__ __forceinline__ void ldsm4(uint32_t* r, uint32_t addr) {
    asm volatile("ldmatrix.sync.aligned.m8n8.x4.shared.b16 {%0,%1,%2,%3}, [%4];"
        : "=r"(r[0]), "=r"(r[1]), "=r"(r[2]), "=r"(r[3]) : "r"(addr));
}
__device__ __forceinline__ void mma16(float* c, const uint32_t* a, const uint32_t* b) {
    asm volatile(
        "mma.sync.aligned.m16n8k16.row.col.f32.bf16.bf16.f32 "
        "{%0,%1,%2,%3}, {%4,%5,%6,%7}, {%8,%9}, {%0,%1,%2,%3};\n"
        : "+f"(c[0]), "+f"(c[1]), "+f"(c[2]), "+f"(c[3])
        : "r"(a[0]), "r"(a[1]), "r"(a[2]), "r"(a[3]), "r"(b[0]), "r"(b[1]));
}

// ---------------- prep kernels ----------------
__device__ __forceinline__ void tconv_body(const float* src, bf16* dst,
                                           int K, int ldsrc, int coloff,
                                           int n0, int k0, int t) {
    __shared__ float sm[32][33];
    #pragma unroll
    for (int p = 0; p < 4; p++) {
        int ki = p*8 + (t >> 5);
        sm[ki][t & 31] = src[(size_t)(k0+ki)*ldsrc + coloff + n0 + (t & 31)];
    }
    __syncthreads();
    #pragma unroll
    for (int p = 0; p < 4; p++) {
        int ni = p*8 + (t >> 5);
        dst[(size_t)(n0+ni)*K + k0 + (t & 31)] = __float2bfloat16(sm[t & 31][ni]);
    }
}

// prepA: W_in (256x1024) -> WinT[1024][256]
__global__ __launch_bounds__(256) void prepA_kernel(const float* __restrict__ W_in) {
    tconv_body(W_in, g_WinT, CDIM, 1024, 0, blockIdx.x*32, blockIdx.y*32, threadIdx.x);
}

// prepBW: WoutT (0..127), Wbc->w2T rows 512..543 (128..143), wcomb rows 0..511 (144..207)
__global__ __launch_bounds__(256) void prepBW_kernel(const float* __restrict__ W_out,
                                                     const float* __restrict__ W_xproj,
                                                     const float* __restrict__ W_dt) {
    int bid = blockIdx.x, t = threadIdx.x;
    if (bid < 128) {
        tconv_body(W_out, g_WoutT, DINNER, 256, 0, (bid & 7)*32, (bid >> 3)*32, t);
    } else if (bid < 144) {
        tconv_body(W_xproj, g_w2T + (size_t)512*DINNER, DINNER, 48, 16, 0,
                   (bid - 128)*32, t);
    } else {
        __shared__ float s_wx[512][17];
        __shared__ float s_wd[16][8];
        const int wb = bid - 144;
        const int n8 = wb*8;
        #pragma unroll
        for (int i = 0; i < 32; i++) {
            int idx = t + i*256;
            s_wx[idx >> 4][idx & 15] = W_xproj[(idx >> 4)*48 + (idx & 15)];
        }
        if (t < 128) s_wd[t >> 3][t & 7] = W_dt[(t >> 3)*DINNER + n8 + (t & 7)];
        __syncthreads();
        const int w = t >> 5, lane = t & 31;
        const int n = n8 + w;
        for (int k = lane; k < DINNER; k += 32) {
            float a = 0.f;
            #pragma unroll
            for (int j = 0; j < 16; j++) a = fmaf(s_wx[k][j], s_wd[j][w], a);
            g_w2T[(size_t)n*DINNER + k] = __float2bfloat16(a);
        }
        uint32_t* zp = (uint32_t*)(g_w2T + (size_t)544*DINNER);
        int i0 = wb*384 + t;
        zp[i0] = 0;
        if (t < 128) zp[i0 + 256] = 0;
    }
}

// ---------------- LayerNorm + (B,C,H,W) -> (B,L,C) bf16 ----------------
__global__ __launch_bounds__(256) void ln_kernel(const float* __restrict__ x,
                                                 const float* __restrict__ gamma,
                                                 const float* __restrict__ beta) {
    __shared__ float sm[32*257];
    __shared__ float s_mu[32], s_rs[32];
    const int b  = blockIdx.x >> 5;
    const int l0 = (blockIdx.x & 31) * 32;
    const int t  = threadIdx.x;
    #pragma unroll
    for (int j = 0; j < 32; j++) {
        int e = j*256 + t;
        sm[(e & 31)*257 + (e >> 5)] = x[((size_t)(b*CDIM + (e >> 5)))*LSEQ + l0 + (e & 31)];
    }
    __syncthreads();
    const int w = t >> 5, lane = t & 31;
    #pragma unroll
    for (int q = 0; q < 4; q++) {
        int li = w*4 + q;
        float s = 0.f, s2 = 0.f;
        #pragma unroll
        for (int j = 0; j < 8; j++) {
            float v = sm[li*257 + lane + j*32];
            s += v; s2 = fmaf(v, v, s2);
        }
        #pragma unroll
        for (int o = 16; o; o >>= 1) {
            s  += __shfl_xor_sync(0xffffffffu, s,  o);
            s2 += __shfl_xor_sync(0xffffffffu, s2, o);
        }
        if (lane == 0) {
            float mu = s * (1.f/CDIM);
            s_mu[li] = mu;
            s_rs[li] = rsqrtf(s2 * (1.f/CDIM) - mu*mu + 1e-5f);
        }
    }
    __syncthreads();
    const float g = gamma[t], be = beta[t];
    #pragma unroll
    for (int li = 0; li < 32; li++) {
        float v = (sm[li*257 + t] - s_mu[li]) * s_rs[li];
        g_xnh[((size_t)(b*LSEQ + l0 + li))*CDIM + t] = __float2bfloat16(fmaf(v, g, be));
    }
}

// ---------------- bf16 mma.sync GEMM, 3-stage cp.async, ldmatrix frags ----------------
// MODE 1: col<512 -> u bf16 (g_uh); col>=512 -> silu -> g_gzh
// MODE 4: combined G2+G3: n0<512 -> (dt,u2) pack -> g_du; n0==512 -> bc pack (wn==0)
// MODE 5: out-fused: smem-transpose fp32 tile, out[b][c][l] = v + x  (Cf=out, e0=x)
template<int MODE>
__global__ __launch_bounds__(256) void gemm_mma(
    const bf16* __restrict__ A, const bf16* __restrict__ Bt,
    float* __restrict__ Cf, const float* __restrict__ e0,
    int K)
{
    constexpr int BM = 128, BN = 128, WM = 64, WN = 32;
    constexpr int BK = 32, ST = 3;
    constexpr int LDA = BK + 8;
    extern __shared__ bf16 sm[];
    bf16* As = sm;
    bf16* Bs = sm + (size_t)ST*BM*LDA;
    const int tid = threadIdx.x, wid = tid >> 5, lane = tid & 31;
    const int g = lane >> 2, q = lane & 3;
    const int wm = wid >> 2, wn = wid & 3;
    const int m0 = blockIdx.y * BM, n0 = blockIdx.x * BN;
    constexpr int MF = WM / 16, NF = WN / 8;
    float acc[MF][NF][4] = {};

    auto load_stage = [&](int s, int kt) {
        const int k0 = kt * BK;
        #pragma unroll
        for (int i = 0; i < BM*4/256; i++) {
            int idx = tid + i*256;
            int r = idx >> 2, c = idx & 3;
            cp16(smem_u32(&As[(s*BM + r)*LDA + c*8]), &A[(size_t)(m0+r)*K + k0 + c*8]);
        }
        #pragma unroll
        for (int i = 0; i < BN*4/256; i++) {
            int idx = tid + i*256;
            int r = idx >> 2, c = idx & 3;
            cp16(smem_u32(&Bs[(s*BN + r)*LDA + c*8]), &Bt[(size_t)(n0+r)*K + k0 + c*8]);
        }
        asm volatile("cp.async.commit_group;\n");
    };
    auto compute = [&](int s) {
        uint32_t aB = smem_u32(As)
            + (uint32_t)(((s*BM + wm*WM + (lane & 15))*LDA + ((lane >> 4) << 3)) * 2);
        uint32_t bB = smem_u32(Bs)
            + (uint32_t)(((s*BN + wn*WN + ((lane >> 4) << 3) + (lane & 7))*LDA
                          + (((lane >> 3) & 1) << 3)) * 2);
        #pragma unroll
        for (int h = 0; h < 2; h++) {
            uint32_t af[MF][4], bfr[NF][2];
            #pragma unroll
            for (int i = 0; i < MF; i++)
                ldsm4(af[i], aB + (uint32_t)((i*16*LDA + h*16) * 2));
            #pragma unroll
            for (int jj = 0; jj < NF/2; jj++) {
                uint32_t tr[4];
                ldsm4(tr, bB + (uint32_t)((jj*16*LDA + h*16) * 2));
                bfr[2*jj][0] = tr[0]; bfr[2*jj][1] = tr[1];
                bfr[2*jj+1][0] = tr[2]; bfr[2*jj+1][1] = tr[3];
            }
            #pragma unroll
            for (int i = 0; i < MF; i++)
                #pragma unroll
                for (int j = 0; j < NF; j++)
                    mma16(acc[i][j], af[i], bfr[j]);
        }
    };

    const int nk = K / BK;
    load_stage(0, 0);
    load_stage(1, 1);
    #pragma unroll 1
    for (int kt = 0; kt < nk; kt++) {
        asm volatile("cp.async.wait_group 1;\n");
        __syncthreads();
        int nx = kt + 2;
        if (nx < nk) load_stage(nx % ST, nx);
        else asm volatile("cp.async.commit_group;\n");
        compute(kt % ST);
    }

    // ----- epilogues -----
    if (MODE == 5) {
        __syncthreads();
        float* smt = (float*)sm;   // 128 x 133 fp32
        #pragma unroll
        for (int i = 0; i < MF; i++) {
            int r = wm*WM + i*16 + g;
            #pragma unroll
            for (int j = 0; j < NF; j++) {
                int c = wn*WN + j*8 + 2*q;
                smt[(size_t)r*133 + c]       = acc[i][j][0];
                smt[(size_t)r*133 + c + 1]   = acc[i][j][1];
                smt[(size_t)(r+8)*133 + c]   = acc[i][j][2];
                smt[(size_t)(r+8)*133 + c+1] = acc[i][j][3];
            }
        }
        __syncthreads();
        const int b = m0 >> 10, l0 = m0 & 1023;
        #pragma unroll 4
        for (int i = 0; i < 64; i++) {
            int idx = tid + i*256;
            int c = idx >> 7, l = idx & 127;
            size_t oi = ((size_t)(b*CDIM + n0 + c))*LSEQ + l0 + l;
            Cf[oi] = smt[(size_t)l*133 + c] + e0[oi];
        }
        return;
    }
    #pragma unroll
    for (int i = 0; i < MF; i++) {
        int row = m0 + wm*WM + i*16 + g;
        if (MODE == 1) {
            #pragma unroll
            for (int j = 0; j < NF; j++) {
                int col = n0 + wn*WN + j*8 + 2*q;
                float v0 = acc[i][j][0], v1 = acc[i][j][1];
                float v2 = acc[i][j][2], v3 = acc[i][j][3];
                if (col < DINNER) {
                    *(uint32_t*)&g_uh[(size_t)(row  )*DINNER + col] = pbf2(v0, v1);
                    *(uint32_t*)&g_uh[(size_t)(row+8)*DINNER + col] = pbf2(v2, v3);
                } else {
                    int cz = col - DINNER;
                    *(uint32_t*)&g_gzh[(size_t)(row  )*DINNER + cz] =
                        pbf2(siluf(v0), siluf(v1));
                    *(uint32_t*)&g_gzh[(size_t)(row+8)*DINNER + cz] =
                        pbf2(siluf(v2), siluf(v3));
                }
            }
        } else if (MODE == 4) {
            if (n0 < DINNER) {
                #pragma unroll
                for (int j = 0; j < NF; j++) {
                    int col = n0 + wn*WN + j*8 + 2*q;
                    float v0 = acc[i][j][0], v1 = acc[i][j][1];
                    float v2 = acc[i][j][2], v3 = acc[i][j][3];
                    float b0 = e0[col], b1 = e0[col+1];
                    uint32_t ua = *(const uint32_t*)&g_u2h[(size_t)(row  )*DINNER + col];
                    uint32_t ub = *(const uint32_t*)&g_u2h[(size_t)(row+8)*DINNER + col];
                    uint32_t d0 = (uint32_t)__bfloat16_as_ushort(__float2bfloat16(softplusf(v0 + b0)));
                    uint32_t d1 = (uint32_t)__bfloat16_as_ushort(__float2bfloat16(softplusf(v1 + b1)));
                    uint32_t d2 = (uint32_t)__bfloat16_as_ushort(__float2bfloat16(softplusf(v2 + b0)));
                    uint32_t d3 = (uint32_t)__bfloat16_as_ushort(__float2bfloat16(softplusf(v3 + b1)));
                    uint2 wa = make_uint2(d0 | ((ua & 0xFFFFu) << 16), d1 | (ua & 0xFFFF0000u));
                    uint2 wb = make_uint2(d2 | ((ub & 0xFFFFu) << 16), d3 | (ub & 0xFFFF0000u));
                    *(uint2*)&g_du[(size_t)(row  )*DINNER + col] = wa;
                    *(uint2*)&g_du[(size_t)(row+8)*DINNER + col] = wb;
                }
            } else if (wn == 0) {
                #pragma unroll
                for (int j = 0; j < 2; j++) {
                    int s = j*8 + 2*q;
                    float4 lo = make_float4(acc[i][j][0], acc[i][j+2][0],
                                            acc[i][j][1], acc[i][j+2][1]);
                    float4 hi = make_float4(acc[i][j][2], acc[i][j+2][2],
                                            acc[i][j][3], acc[i][j+2][3]);
                    *(float4*)&g_bc[(size_t)(row  )*DSTATE + s] = lo;
                    *(float4*)&g_bc[(size_t)(row+8)*DSTATE + s] = hi;
                }
            }
        }
    }
}

// ---------------- depthwise causal conv (D_CONV=4) + SiLU, bf162 ----------------
__global__ __launch_bounds__(256) void conv_silu_kernel(const float* __restrict__ cw,
                                                        const float* __restrict__ cb) {
    int gid = blockIdx.x*256 + threadIdx.x;
    int d2  = gid & 255;
    int row = gid >> 8;
    int l   = row & (LSEQ-1);
    int d   = d2 * 2;
    float a0 = cb[d], a1 = cb[d+1];
    const uint32_t* up = (const uint32_t*)g_uh;
    #pragma unroll
    for (int k = 0; k < 4; k++) {
        int ll = l - 3 + k;
        if (ll >= 0) {
            uint32_t w = up[(size_t)(row - 3 + k)*256 + d2];
            bf162 p = *(bf162*)&w;
            a0 = fmaf(__bfloat162float(p.x), cw[d*4 + k],     a0);
            a1 = fmaf(__bfloat162float(p.y), cw[(d+1)*4 + k], a1);
        }
    }
    ((uint32_t*)g_u2h)[gid] = pbf2(siluf(a0), siluf(a1));
}

// ---------------- selective scan v5: 1 sync/chunk, smem transpose-reduce ----------
// block = 256 thr = 8 warps; batch b = blockIdx>>5, channels dblk..dblk+15.
// warp = 2 chains (ch = 2*widx + half), 16-lane group = states s=0..15.
// Double-buffered tiles; reduction via per-warp smem transpose + tree sum
// (lane s ends with the sum for step j=s); yg flush deferred one chunk.
__global__ __launch_bounds__(256) void scan_kernel(const float* __restrict__ A_log,
                                                   const float* __restrict__ D_skip) {
    __shared__ uint32_t       s_du[2][16][16];
    __shared__ float2         s_bc[2][16][16];
    __shared__ unsigned short s_gz[2][16][16];
    __shared__ unsigned short s_yg[2][16][16];
    __shared__ float          s_p [8][2][16][17];
    const int b    = blockIdx.x >> 5;
    const int dblk = (blockIdx.x & 31) * 16;
    const int tid  = threadIdx.x;
    const int widx = tid >> 5, lane = tid & 31;
    const int half = lane >> 4, s = lane & 15;
    const int ch   = 2*widx + half;
    const int d    = dblk + ch;
    const float Aval = -__expf(A_log[d*DSTATE + s]);
    const float Dd   = D_skip[d];
    const size_t rb  = (size_t)b * LSEQ;
    const int li = tid >> 4, dd = tid & 15;
    const uint32_t*       duG = g_du;
    const unsigned short* gzG = (const unsigned short*)g_gzh;
    unsigned short*       ygG = (unsigned short*)g_ygh;
    float* pbase = &s_p[widx][half][0][0];

    uint32_t r_du; unsigned short r_gz; float2 r_bc;
    auto ldchunk = [&](int c0) {
        size_t rw = (rb + c0 + li);
        r_du = duG[rw*DINNER + dblk + dd];
        r_gz = gzG[rw*DINNER + dblk + dd];
        r_bc = g_bc[rw*DSTATE + dd];
    };
    float h = 0.f;
    ldchunk(0);
    #pragma unroll 1
    for (int k = 0; k < 64; k++) {
        const int cb = k & 1;
        s_du[cb][li][dd] = r_du;
        s_gz[cb][li][dd] = r_gz;
        s_bc[cb][li][dd] = r_bc;
        __syncthreads();
        // deferred flush of previous chunk's outputs (overlaps this chunk's compute)
        if (k > 0)
            ygG[(rb + (k-1)*16 + li)*DINNER + dblk + dd] = s_yg[cb ^ 1][li][dd];
        if (k < 63) ldchunk((k+1)*16);
        // Phase A: recurrence (ILP across loads/exps; serial h-chain only)
        float p[16];
        #pragma unroll
        for (int j = 0; j < 16; j++) {
            uint32_t w = s_du[cb][j][ch];
            bf162 pk = *(bf162*)&w;
            float dt = __bfloat162float(pk.x);
            float u2 = __bfloat162float(pk.y);
            float2 bcv = s_bc[cb][j][s];
            float dA = __expf(dt * Aval);
            h = fmaf(dA, h, dt * u2 * bcv.x);
            p[j] = h * bcv.y;
        }
        // Phase B: smem transpose-reduce (conflict-free rows stride 17)
        #pragma unroll
        for (int j = 0; j < 16; j++) pbase[s*17 + j] = p[j];
        __syncwarp();
        float t[16];
        #pragma unroll
        for (int j2 = 0; j2 < 16; j2++) t[j2] = pbase[j2*17 + s];
        #pragma unroll
        for (int st = 1; st < 16; st <<= 1)
            #pragma unroll
            for (int j2 = 0; j2 < 16; j2 += 2*st) t[j2] += t[j2 + st];
        // Phase C: lane s owns step j = s
        {
            uint32_t w = s_du[cb][s][ch];
            bf162 pk = *(bf162*)&w;
            float u2 = __bfloat162float(pk.y);
            float yv = t[0] + u2 * Dd;
            float gzf = __bfloat162float(__ushort_as_bfloat16(s_gz[cb][s][ch]));
            s_yg[cb][s][ch] = __bfloat16_as_ushort(__float2bfloat16(yv * gzf));
        }
    }
    __syncthreads();
    ygG[(rb + 63*16 + li)*DINNER + dblk + dd] = s_yg[1][li][dd];
}

// ---------------- host launch ----------------
extern "C" void kernel_launch(void* const* d_in, const int* in_sizes, int n_in,
                              void* d_out, int out_size) {
    const float* x       = (const float*)d_in[0];
    const float* ln_g    = (const float*)d_in[1];
    const float* ln_b    = (const float*)d_in[2];
    const float* W_in    = (const float*)d_in[3];
    const float* conv_w  = (const float*)d_in[4];
    const float* conv_b  = (const float*)d_in[5];
    const float* W_xproj = (const float*)d_in[6];
    const float* W_dt    = (const float*)d_in[7];
    const float* b_dt    = (const float*)d_in[8];
    const float* A_log   = (const float*)d_in[9];
    const float* D_skip  = (const float*)d_in[10];
    const float* W_out   = (const float*)d_in[11];
    float* out = (float*)d_out;

    bf16 *p_xnh, *p_u2h, *p_ygh, *p_WinT, *p_w2T, *p_WoutT;
    cudaGetSymbolAddress((void**)&p_xnh,   g_xnh);
    cudaGetSymbolAddress((void**)&p_u2h,   g_u2h);
    cudaGetSymbolAddress((void**)&p_ygh,   g_ygh);
    cudaGetSymbolAddress((void**)&p_WinT,  g_WinT);
    cudaGetSymbolAddress((void**)&p_w2T,   g_w2T);
    cudaGetSymbolAddress((void**)&p_WoutT, g_WoutT);

    const int SMB = 3*(128+128)*40*2;          // 61440 pipeline
    const int SMO = 128*133*4;                 // 68096 for MODE 5
    cudaFuncSetAttribute(gemm_mma<1>, cudaFuncAttributeMaxDynamicSharedMemorySize, SMB);
    cudaFuncSetAttribute(gemm_mma<4>, cudaFuncAttributeMaxDynamicSharedMemorySize, SMB);
    cudaFuncSetAttribute(gemm_mma<5>, cudaFuncAttributeMaxDynamicSharedMemorySize, SMO);

    // launch index (ncu captures index 3 = G1):
    ln_kernel<<<BATCH*32, 256>>>(x, ln_g, ln_b);                       // 0
    prepA_kernel<<<dim3(32, 8), 256>>>(W_in);                          // 1
    prepBW_kernel<<<208, 256>>>(W_out, W_xproj, W_dt);                 // 2
    gemm_mma<1><<<dim3(8, 64), 256, SMB>>>(                            // 3  G1
        p_xnh, p_WinT, nullptr, nullptr, CDIM);
    conv_silu_kernel<<<NROWS, 256>>>(conv_w, conv_b);                  // 4
    gemm_mma<4><<<dim3(5, 64), 256, SMB>>>(                            // 5  G2+G3
        p_u2h, p_w2T, nullptr, b_dt, DINNER);
    scan_kernel<<<256, 256>>>(A_log, D_skip);                          // 6
    gemm_mma<5><<<dim3(2, 64), 256, SMO>>>(                            // 7  G4+out
        p_ygh, p_WoutT, out, x, DINNER);
}

// round 13
// speedup vs baseline: 1.4551x; 1.0792x over previous
#include <cuda_runtime.h>
#include <cuda_bf16.h>
#include <math.h>
#include <stdint.h>

// ---------------- problem constants ----------------
#define LSEQ   1024
#define BATCH  8
#define CDIM   256
#define DINNER 512
#define DSTATE 16
#define NROWS  (BATCH*LSEQ)   // 8192

typedef __nv_bfloat16 bf16;
typedef __nv_bfloat162 bf162;

// ---------------- scratch (static, no allocs) ----------------
__device__ __align__(256) bf16     g_xnh  [(size_t)NROWS*CDIM];
__device__ __align__(256) bf16     g_uh   [(size_t)NROWS*DINNER];
__device__ __align__(256) bf16     g_gzh  [(size_t)NROWS*DINNER];   // silu(z), [row][d]
__device__ __align__(256) bf16     g_u2h  [(size_t)NROWS*DINNER];
__device__ __align__(256) uint32_t g_du   [(size_t)NROWS*DINNER];   // (dt,u2) pack, [row][d]
__device__ __align__(256) float2   g_bc   [(size_t)NROWS*DSTATE];   // [row][s]
__device__ __align__(256) bf16     g_ygh  [(size_t)NROWS*DINNER];   // [row][d]
// weights, bf16, K-major [N][K]
__device__ __align__(256) bf16     g_WinT  [(size_t)1024*CDIM];
__device__ __align__(256) bf16     g_w2T   [(size_t)640*DINNER];    // [0:512)=wcomb, [512:544)=Wbc, rest 0
__device__ __align__(256) bf16     g_WoutT [(size_t)CDIM*DINNER];

// ---------------- small helpers ----------------
__device__ __forceinline__ float siluf(float v) { return v / (1.f + __expf(-v)); }
__device__ __forceinline__ float softplusf(float v) {
    return (v > 20.f) ? v : log1pf(__expf(v));
}
__device__ __forceinline__ uint32_t pbf2(float lo, float hi) {
    uint32_t r;
    asm("cvt.rn.bf16x2.f32 %0, %1, %2;" : "=r"(r) : "f"(hi), "f"(lo));
    return r;
}
__device__ __forceinline__ uint32_t smem_u32(const void* p) {
    return (uint32_t)__cvta_generic_to_shared(p);
}
__device__ __forceinline__ void cp16(uint32_t sm, const void* gm) {
    asm volatile("cp.async.cg.shared.global [%0], [%1], 16;\n" :: "r"(sm), "l"(gm));
}
__device__ __forceinline__ void ldsm4(uint32_t* r, uint32_t addr) {
    asm volatile("ldmatrix.sync.aligned.m8n8.x4.shared.b16 {%0,%1,%2,%3}, [%4];"
        : "=r"(r[0]), "=r"(r[1]), "=r"(r[2]), "=r"(r[3]) : "r"(addr));
}
__device__ __forceinline__ void mma16(float* c, const uint32_t* a, const uint32_t* b) {
    asm volatile(
        "mma.sync.aligned.m16n8k16.row.col.f32.bf16.bf16.f32 "
        "{%0,%1,%2,%3}, {%4,%5,%6,%7}, {%8,%9}, {%0,%1,%2,%3};\n"
        : "+f"(c[0]), "+f"(c[1]), "+f"(c[2]), "+f"(c[3])
        : "r"(a[0]), "r"(a[1]), "r"(a[2]), "r"(a[3]), "r"(b[0]), "r"(b[1]));
}

// ---------------- merged prep kernel: ln + prepA + prepBW (independent) ----------
// blocks 0..255   : LayerNorm + transpose -> g_xnh
// blocks 256..511 : W_in -> WinT
// blocks 512..639 : W_out -> WoutT
// blocks 640..655 : W_xproj[:,16:48] -> w2T rows 512..543
// blocks 656..719 : wcomb -> w2T rows 0..511 + zero pad rows 544..639
__device__ __forceinline__ void tconv_body(char* smc, const float* src, bf16* dst,
                                           int K, int ldsrc, int coloff,
                                           int n0, int k0, int t) {
    float (*sm)[33] = (float(*)[33])smc;
    #pragma unroll
    for (int p = 0; p < 4; p++) {
        int ki = p*8 + (t >> 5);
        sm[ki][t & 31] = src[(size_t)(k0+ki)*ldsrc + coloff + n0 + (t & 31)];
    }
    __syncthreads();
    #pragma unroll
    for (int p = 0; p < 4; p++) {
        int ni = p*8 + (t >> 5);
        dst[(size_t)(n0+ni)*K + k0 + (t & 31)] = __float2bfloat16(sm[t & 31][ni]);
    }
}

__global__ __launch_bounds__(256) void prep_kernel(
    const float* __restrict__ x, const float* __restrict__ gamma,
    const float* __restrict__ beta, const float* __restrict__ W_in,
    const float* __restrict__ W_out, const float* __restrict__ W_xproj,
    const float* __restrict__ W_dt)
{
    __shared__ __align__(16) char smc[35840];
    const int bid = blockIdx.x, t = threadIdx.x;
    if (bid < 256) {
        // ---- LayerNorm ----
        float* sm   = (float*)smc;              // 32*257
        float* s_mu = sm + 32*257;
        float* s_rs = s_mu + 32;
        const int b  = bid >> 5;
        const int l0 = (bid & 31) * 32;
        #pragma unroll
        for (int j = 0; j < 32; j++) {
            int e = j*256 + t;
            sm[(e & 31)*257 + (e >> 5)] =
                x[((size_t)(b*CDIM + (e >> 5)))*LSEQ + l0 + (e & 31)];
        }
        __syncthreads();
        const int w = t >> 5, lane = t & 31;
        #pragma unroll
        for (int q = 0; q < 4; q++) {
            int li = w*4 + q;
            float s = 0.f, s2 = 0.f;
            #pragma unroll
            for (int j = 0; j < 8; j++) {
                float v = sm[li*257 + lane + j*32];
                s += v; s2 = fmaf(v, v, s2);
            }
            #pragma unroll
            for (int o = 16; o; o >>= 1) {
                s  += __shfl_xor_sync(0xffffffffu, s,  o);
                s2 += __shfl_xor_sync(0xffffffffu, s2, o);
            }
            if (lane == 0) {
                float mu = s * (1.f/CDIM);
                s_mu[li] = mu;
                s_rs[li] = rsqrtf(s2 * (1.f/CDIM) - mu*mu + 1e-5f);
            }
        }
        __syncthreads();
        const float g = gamma[t], be = beta[t];
        #pragma unroll
        for (int li = 0; li < 32; li++) {
            float v = (sm[li*257 + t] - s_mu[li]) * s_rs[li];
            g_xnh[((size_t)(b*LSEQ + l0 + li))*CDIM + t] =
                __float2bfloat16(fmaf(v, g, be));
        }
    } else if (bid < 512) {
        int i = bid - 256;
        tconv_body(smc, W_in, g_WinT, CDIM, 1024, 0, (i & 31)*32, (i >> 5)*32, t);
    } else if (bid < 640) {
        int i = bid - 512;
        tconv_body(smc, W_out, g_WoutT, DINNER, 256, 0, (i & 7)*32, (i >> 3)*32, t);
    } else if (bid < 656) {
        tconv_body(smc, W_xproj, g_w2T + (size_t)512*DINNER, DINNER, 48, 16, 0,
                   (bid - 640)*32, t);
    } else {
        // ---- wcomb ----
        float (*s_wx)[17] = (float(*)[17])smc;           // 512 x 17
        float (*s_wd)[8]  = (float(*)[8])(smc + 512*17*4);
        const int wb = bid - 656;
        const int n8 = wb*8;
        #pragma unroll
        for (int i = 0; i < 32; i++) {
            int idx = t + i*256;
            s_wx[idx >> 4][idx & 15] = W_xproj[(idx >> 4)*48 + (idx & 15)];
        }
        if (t < 128) s_wd[t >> 3][t & 7] = W_dt[(t >> 3)*DINNER + n8 + (t & 7)];
        __syncthreads();
        const int w = t >> 5, lane = t & 31;
        const int n = n8 + w;
        for (int k = lane; k < DINNER; k += 32) {
            float a = 0.f;
            #pragma unroll
            for (int j = 0; j < 16; j++) a = fmaf(s_wx[k][j], s_wd[j][w], a);
            g_w2T[(size_t)n*DINNER + k] = __float2bfloat16(a);
        }
        uint32_t* zp = (uint32_t*)(g_w2T + (size_t)544*DINNER);
        int i0 = wb*384 + t;
        zp[i0] = 0;
        if (t < 128) zp[i0 + 256] = 0;
    }
}

// ---------------- bf16 mma.sync GEMM, 3-stage cp.async, batched LDSM ----------------
// MODE 1: col<512 -> u bf16 (g_uh); col>=512 -> silu -> g_gzh
// MODE 4: combined G2+G3: n0<512 -> (dt,u2) pack -> g_du; n0==512 -> bc pack (wn==0)
// MODE 5: out-fused: smem-transpose fp32 tile, out[b][c][l] = v + x  (Cf=out, e0=x)
template<int MODE>
__global__ __launch_bounds__(256, 2) void gemm_mma(
    const bf16* __restrict__ A, const bf16* __restrict__ Bt,
    float* __restrict__ Cf, const float* __restrict__ e0,
    int K)
{
    constexpr int BM = 128, BN = 128, WM = 64, WN = 32;
    constexpr int BK = 32, ST = 3;
    constexpr int LDA = BK + 8;
    extern __shared__ bf16 sm[];
    bf16* As = sm;
    bf16* Bs = sm + (size_t)ST*BM*LDA;
    const int tid = threadIdx.x, wid = tid >> 5, lane = tid & 31;
    const int g = lane >> 2, q = lane & 3;
    const int wm = wid >> 2, wn = wid & 3;
    const int m0 = blockIdx.y * BM, n0 = blockIdx.x * BN;
    constexpr int MF = WM / 16, NF = WN / 8;
    float acc[MF][NF][4] = {};

    auto load_stage = [&](int s, int kt) {
        const int k0 = kt * BK;
        #pragma unroll
        for (int i = 0; i < BM*4/256; i++) {
            int idx = tid + i*256;
            int r = idx >> 2, c = idx & 3;
            cp16(smem_u32(&As[(s*BM + r)*LDA + c*8]), &A[(size_t)(m0+r)*K + k0 + c*8]);
        }
        #pragma unroll
        for (int i = 0; i < BN*4/256; i++) {
            int idx = tid + i*256;
            int r = idx >> 2, c = idx & 3;
            cp16(smem_u32(&Bs[(s*BN + r)*LDA + c*8]), &Bt[(size_t)(n0+r)*K + k0 + c*8]);
        }
        asm volatile("cp.async.commit_group;\n");
    };
    auto compute = [&](int s) {
        uint32_t aB = smem_u32(As)
            + (uint32_t)(((s*BM + wm*WM + (lane & 15))*LDA + ((lane >> 4) << 3)) * 2);
        uint32_t bB = smem_u32(Bs)
            + (uint32_t)(((s*BN + wn*WN + ((lane >> 4) << 3) + (lane & 7))*LDA
                          + (((lane >> 3) & 1) << 3)) * 2);
        // batch ALL fragment loads (both K-halves) for maximal LDSM ILP,
        // then run the 64-mma burst uninterrupted.
        uint32_t af[2][MF][4], bfr[2][NF][2];
        #pragma unroll
        for (int h = 0; h < 2; h++) {
            #pragma unroll
            for (int i = 0; i < MF; i++)
                ldsm4(af[h][i], aB + (uint32_t)((i*16*LDA + h*16) * 2));
            #pragma unroll
            for (int jj = 0; jj < NF/2; jj++) {
                uint32_t tr[4];
                ldsm4(tr, bB + (uint32_t)((jj*16*LDA + h*16) * 2));
                bfr[h][2*jj][0] = tr[0]; bfr[h][2*jj][1] = tr[1];
                bfr[h][2*jj+1][0] = tr[2]; bfr[h][2*jj+1][1] = tr[3];
            }
        }
        #pragma unroll
        for (int h = 0; h < 2; h++)
            #pragma unroll
            for (int i = 0; i < MF; i++)
                #pragma unroll
                for (int j = 0; j < NF; j++)
                    mma16(acc[i][j], af[h][i], bfr[h][j]);
    };

    const int nk = K / BK;
    load_stage(0, 0);
    load_stage(1, 1);
    #pragma unroll 1
    for (int kt = 0; kt < nk; kt++) {
        asm volatile("cp.async.wait_group 1;\n");
        __syncthreads();
        int nx = kt + 2;
        if (nx < nk) load_stage(nx % ST, nx);
        else asm volatile("cp.async.commit_group;\n");
        compute(kt % ST);
    }

    // ----- epilogues -----
    if (MODE == 5) {
        __syncthreads();
        float* smt = (float*)sm;   // 128 x 133 fp32
        #pragma unroll
        for (int i = 0; i < MF; i++) {
            int r = wm*WM + i*16 + g;
            #pragma unroll
            for (int j = 0; j < NF; j++) {
                int c = wn*WN + j*8 + 2*q;
                smt[(size_t)r*133 + c]       = acc[i][j][0];
                smt[(size_t)r*133 + c + 1]   = acc[i][j][1];
                smt[(size_t)(r+8)*133 + c]   = acc[i][j][2];
                smt[(size_t)(r+8)*133 + c+1] = acc[i][j][3];
            }
        }
        __syncthreads();
        const int b = m0 >> 10, l0 = m0 & 1023;
        #pragma unroll 4
        for (int i = 0; i < 64; i++) {
            int idx = tid + i*256;
            int c = idx >> 7, l = idx & 127;
            size_t oi = ((size_t)(b*CDIM + n0 + c))*LSEQ + l0 + l;
            Cf[oi] = smt[(size_t)l*133 + c] + e0[oi];
        }
        return;
    }
    #pragma unroll
    for (int i = 0; i < MF; i++) {
        int row = m0 + wm*WM + i*16 + g;
        if (MODE == 1) {
            #pragma unroll
            for (int j = 0; j < NF; j++) {
                int col = n0 + wn*WN + j*8 + 2*q;
                float v0 = acc[i][j][0], v1 = acc[i][j][1];
                float v2 = acc[i][j][2], v3 = acc[i][j][3];
                if (col < DINNER) {
                    *(uint32_t*)&g_uh[(size_t)(row  )*DINNER + col] = pbf2(v0, v1);
                    *(uint32_t*)&g_uh[(size_t)(row+8)*DINNER + col] = pbf2(v2, v3);
                } else {
                    int cz = col - DINNER;
                    *(uint32_t*)&g_gzh[(size_t)(row  )*DINNER + cz] =
                        pbf2(siluf(v0), siluf(v1));
                    *(uint32_t*)&g_gzh[(size_t)(row+8)*DINNER + cz] =
                        pbf2(siluf(v2), siluf(v3));
                }
            }
        } else if (MODE == 4) {
            if (n0 < DINNER) {
                #pragma unroll
                for (int j = 0; j < NF; j++) {
                    int col = n0 + wn*WN + j*8 + 2*q;
                    float v0 = acc[i][j][0], v1 = acc[i][j][1];
                    float v2 = acc[i][j][2], v3 = acc[i][j][3];
                    float b0 = e0[col], b1 = e0[col+1];
                    uint32_t ua = *(const uint32_t*)&g_u2h[(size_t)(row  )*DINNER + col];
                    uint32_t ub = *(const uint32_t*)&g_u2h[(size_t)(row+8)*DINNER + col];
                    uint32_t d0 = (uint32_t)__bfloat16_as_ushort(__float2bfloat16(softplusf(v0 + b0)));
                    uint32_t d1 = (uint32_t)__bfloat16_as_ushort(__float2bfloat16(softplusf(v1 + b1)));
                    uint32_t d2 = (uint32_t)__bfloat16_as_ushort(__float2bfloat16(softplusf(v2 + b0)));
                    uint32_t d3 = (uint32_t)__bfloat16_as_ushort(__float2bfloat16(softplusf(v3 + b1)));
                    uint2 wa = make_uint2(d0 | ((ua & 0xFFFFu) << 16), d1 | (ua & 0xFFFF0000u));
                    uint2 wb = make_uint2(d2 | ((ub & 0xFFFFu) << 16), d3 | (ub & 0xFFFF0000u));
                    *(uint2*)&g_du[(size_t)(row  )*DINNER + col] = wa;
                    *(uint2*)&g_du[(size_t)(row+8)*DINNER + col] = wb;
                }
            } else if (wn == 0) {
                #pragma unroll
                for (int j = 0; j < 2; j++) {
                    int s = j*8 + 2*q;
                    float4 lo = make_float4(acc[i][j][0], acc[i][j+2][0],
                                            acc[i][j][1], acc[i][j+2][1]);
                    float4 hi = make_float4(acc[i][j][2], acc[i][j+2][2],
                                            acc[i][j][3], acc[i][j+2][3]);
                    *(float4*)&g_bc[(size_t)(row  )*DSTATE + s] = lo;
                    *(float4*)&g_bc[(size_t)(row+8)*DSTATE + s] = hi;
                }
            }
        }
    }
}

// ---------------- depthwise causal conv (D_CONV=4) + SiLU, bf162 ----------------
__global__ __launch_bounds__(256) void conv_silu_kernel(const float* __restrict__ cw,
                                                        const float* __restrict__ cb) {
    int gid = blockIdx.x*256 + threadIdx.x;
    int d2  = gid & 255;
    int row = gid >> 8;
    int l   = row & (LSEQ-1);
    int d   = d2 * 2;
    float a0 = cb[d], a1 = cb[d+1];
    const uint32_t* up = (const uint32_t*)g_uh;
    #pragma unroll
    for (int k = 0; k < 4; k++) {
        int ll = l - 3 + k;
        if (ll >= 0) {
            uint32_t w = up[(size_t)(row - 3 + k)*256 + d2];
            bf162 p = *(bf162*)&w;
            a0 = fmaf(__bfloat162float(p.x), cw[d*4 + k],     a0);
            a1 = fmaf(__bfloat162float(p.y), cw[(d+1)*4 + k], a1);
        }
    }
    ((uint32_t*)g_u2h)[gid] = pbf2(siluf(a0), siluf(a1));
}

// ---------------- selective scan v5 (verified R12) ----------------
__global__ __launch_bounds__(256) void scan_kernel(const float* __restrict__ A_log,
                                                   const float* __restrict__ D_skip) {
    __shared__ uint32_t       s_du[2][16][16];
    __shared__ float2         s_bc[2][16][16];
    __shared__ unsigned short s_gz[2][16][16];
    __shared__ unsigned short s_yg[2][16][16];
    __shared__ float          s_p [8][2][16][17];
    const int b    = blockIdx.x >> 5;
    const int dblk = (blockIdx.x & 31) * 16;
    const int tid  = threadIdx.x;
    const int widx = tid >> 5, lane = tid & 31;
    const int half = lane >> 4, s = lane & 15;
    const int ch   = 2*widx + half;
    const int d    = dblk + ch;
    const float Aval = -__expf(A_log[d*DSTATE + s]);
    const float Dd   = D_skip[d];
    const size_t rb  = (size_t)b * LSEQ;
    const int li = tid >> 4, dd = tid & 15;
    const uint32_t*       duG = g_du;
    const unsigned short* gzG = (const unsigned short*)g_gzh;
    unsigned short*       ygG = (unsigned short*)g_ygh;
    float* pbase = &s_p[widx][half][0][0];

    uint32_t r_du; unsigned short r_gz; float2 r_bc;
    auto ldchunk = [&](int c0) {
        size_t rw = (rb + c0 + li);
        r_du = duG[rw*DINNER + dblk + dd];
        r_gz = gzG[rw*DINNER + dblk + dd];
        r_bc = g_bc[rw*DSTATE + dd];
    };
    float h = 0.f;
    ldchunk(0);
    #pragma unroll 1
    for (int k = 0; k < 64; k++) {
        const int cb = k & 1;
        s_du[cb][li][dd] = r_du;
        s_gz[cb][li][dd] = r_gz;
        s_bc[cb][li][dd] = r_bc;
        __syncthreads();
        if (k > 0)
            ygG[(rb + (k-1)*16 + li)*DINNER + dblk + dd] = s_yg[cb ^ 1][li][dd];
        if (k < 63) ldchunk((k+1)*16);
        float p[16];
        #pragma unroll
        for (int j = 0; j < 16; j++) {
            uint32_t w = s_du[cb][j][ch];
            bf162 pk = *(bf162*)&w;
            float dt = __bfloat162float(pk.x);
            float u2 = __bfloat162float(pk.y);
            float2 bcv = s_bc[cb][j][s];
            float dA = __expf(dt * Aval);
            h = fmaf(dA, h, dt * u2 * bcv.x);
            p[j] = h * bcv.y;
        }
        #pragma unroll
        for (int j = 0; j < 16; j++) pbase[s*17 + j] = p[j];
        __syncwarp();
        float t[16];
        #pragma unroll
        for (int j2 = 0; j2 < 16; j2++) t[j2] = pbase[j2*17 + s];
        #pragma unroll
        for (int st = 1; st < 16; st <<= 1)
            #pragma unroll
            for (int j2 = 0; j2 < 16; j2 += 2*st) t[j2] += t[j2 + st];
        {
            uint32_t w = s_du[cb][s][ch];
            bf162 pk = *(bf162*)&w;
            float u2 = __bfloat162float(pk.y);
            float yv = t[0] + u2 * Dd;
            float gzf = __bfloat162float(__ushort_as_bfloat16(s_gz[cb][s][ch]));
            s_yg[cb][s][ch] = __bfloat16_as_ushort(__float2bfloat16(yv * gzf));
        }
    }
    __syncthreads();
    ygG[(rb + 63*16 + li)*DINNER + dblk + dd] = s_yg[1][li][dd];
}

// ---------------- host launch ----------------
extern "C" void kernel_launch(void* const* d_in, const int* in_sizes, int n_in,
                              void* d_out, int out_size) {
    const float* x       = (const float*)d_in[0];
    const float* ln_g    = (const float*)d_in[1];
    const float* ln_b    = (const float*)d_in[2];
    const float* W_in    = (const float*)d_in[3];
    const float* conv_w  = (const float*)d_in[4];
    const float* conv_b  = (const float*)d_in[5];
    const float* W_xproj = (const float*)d_in[6];
    const float* W_dt    = (const float*)d_in[7];
    const float* b_dt    = (const float*)d_in[8];
    const float* A_log   = (const float*)d_in[9];
    const float* D_skip  = (const float*)d_in[10];
    const float* W_out   = (const float*)d_in[11];
    float* out = (float*)d_out;

    bf16 *p_xnh, *p_u2h, *p_ygh, *p_WinT, *p_w2T, *p_WoutT;
    cudaGetSymbolAddress((void**)&p_xnh,   g_xnh);
    cudaGetSymbolAddress((void**)&p_u2h,   g_u2h);
    cudaGetSymbolAddress((void**)&p_ygh,   g_ygh);
    cudaGetSymbolAddress((void**)&p_WinT,  g_WinT);
    cudaGetSymbolAddress((void**)&p_w2T,   g_w2T);
    cudaGetSymbolAddress((void**)&p_WoutT, g_WoutT);

    const int SMB = 3*(128+128)*40*2;          // 61440 pipeline
    const int SMO = 128*133*4;                 // 68096 for MODE 5
    cudaFuncSetAttribute(gemm_mma<1>, cudaFuncAttributeMaxDynamicSharedMemorySize, SMB);
    cudaFuncSetAttribute(gemm_mma<4>, cudaFuncAttributeMaxDynamicSharedMemorySize, SMB);
    cudaFuncSetAttribute(gemm_mma<5>, cudaFuncAttributeMaxDynamicSharedMemorySize, SMO);

    // launch index (ncu captures index 3 = G2 this round):
    prep_kernel<<<720, 256>>>(x, ln_g, ln_b, W_in, W_out, W_xproj, W_dt);  // 0
    gemm_mma<1><<<dim3(8, 64), 256, SMB>>>(                                // 1  G1
        p_xnh, p_WinT, nullptr, nullptr, CDIM);
    conv_silu_kernel<<<NROWS, 256>>>(conv_w, conv_b);                      // 2
    gemm_mma<4><<<dim3(5, 64), 256, SMB>>>(                                // 3  G2+G3
        p_u2h, p_w2T, nullptr, b_dt, DINNER);
    scan_kernel<<<256, 256>>>(A_log, D_skip);                              // 4
    gemm_mma<5><<<dim3(2, 64), 256, SMO>>>(                                // 5  G4+out
        p_ygh, p_WoutT, out, x, DINNER);
}